// round 2
// baseline (speedup 1.0000x reference)
#include <cuda_runtime.h>
#include <cstdlib>

// Problem constants (from reference):
//   H=16, N=2^16, T=128, S=128, C=257, TP=8
// Inputs (metadata order):
//   d_in[0] sta_loc  int32  (T, TP)
//   d_in[1] pos_loc  int32  (T, S, TP)
//   d_in[2] cnc_loc  int32  (T, C, TP)
//   d_in[3] eu_norm  fp32   (T, S)
// Output: ct_val fp32 (T, S, C, TP) = 33,685,504 elems = 134.7 MB
//
// ct_val[t,s,c,p] = (sum_q d_sta_pos[t,s,q] - d_sta_pos[t,s,p] + d_cnc_pos[t,s,c,p]) / TP
// where d(c1,c2,norm) = sgn(c1)sgn(c2) * (1 - frexp_exp(|c1|^|c2| + 1)/H) * norm
// frexp_exp(x) for integer x in [1, 2^16] == 32 - clz(x)   (exact)

#define TT 128
#define SS 128
#define CC 257
#define TP 8

__global__ __launch_bounds__(256, 8)
void critigraph_kernel(const int*   __restrict__ sta,
                       const int*   __restrict__ pos,
                       const int*   __restrict__ cnc,
                       const float* __restrict__ eu,
                       float*       __restrict__ out)
{
    const int ts  = blockIdx.x;        // ts = t*S + s
    const int t   = ts >> 7;           // S = 128
    const int tid = threadIdx.x;

    __shared__ float s_base[TP];   // (sum - d_sta[p]) / TP
    __shared__ int   s_pabs[TP];   // |pos[t,s,p]|
    __shared__ float s_fscl[TP];   // sgn(pos[t,s,p]) * norm / TP

    // ---- per-(t,s) precompute: warp 0 only -------------------------------
    if (tid < 32) {
        float d  = 0.0f;
        int   pv = 0;
        const float norm = eu[ts];
        if (tid < TP) {
            const int sv = sta[t * TP + tid];
            pv = pos[ts * TP + tid];
            const int x = (abs(sv) ^ abs(pv)) + 1;          // in [1, 65536]
            const int e = 32 - __clz(x);                    // frexp exponent
            float f = 1.0f - (float)e * (1.0f / 16.0f);
            // sign product: negative iff sign bits differ (values never 0-ambiguous:
            // reference treats >=0 as +1, and abs/xor path is sign-independent)
            d = ((sv ^ pv) < 0) ? (-f * norm) : (f * norm);
            d = ((sv < 0) == (pv < 0)) ? fabsf(d) * ((f < 0.f) ? -1.f : 1.f) * ((norm < 0.f) ? -1.f : 1.f) : d; // no-op guard removed below
            // (the line above is redundant; keep simple form)
            d = ((sv < 0) != (pv < 0)) ? -f * norm : f * norm;
        }
        // butterfly sum over the 8 data lanes (lanes 8..31 carry 0)
        float sum = d;
        #pragma unroll
        for (int m = 1; m < TP; m <<= 1)
            sum += __shfl_xor_sync(0xffffffffu, sum, m);
        if (tid < TP) {
            s_base[tid] = (sum - d) * (1.0f / TP);
            s_pabs[tid] = abs(pv);
            s_fscl[tid] = ((pv >= 0) ? norm : -norm) * (1.0f / TP);
        }
    }
    __syncthreads();

    // broadcast shared -> registers (uniform across block)
    float base[TP], fscl[TP];
    int   pabs[TP];
    #pragma unroll
    for (int p = 0; p < TP; ++p) {
        base[p] = s_base[p];
        pabs[p] = s_pabs[p];
        fscl[p] = s_fscl[p];
    }

    // ---- main loop: one candidate c per thread, 8 outputs each -----------
    for (int c = tid; c < CC; c += 256) {
        const int4* cp = reinterpret_cast<const int4*>(cnc + ((size_t)t * CC + c) * TP);
        const int4 a = __ldg(cp);
        const int4 b = __ldg(cp + 1);
        const int cv[TP] = {a.x, a.y, a.z, a.w, b.x, b.y, b.z, b.w};

        float r[TP];
        #pragma unroll
        for (int p = 0; p < TP; ++p) {
            const int cc = cv[p];
            const int x  = (abs(cc) ^ pabs[p]) + 1;
            float f = 1.0f - (float)(32 - __clz(x)) * (1.0f / 16.0f);
            f = (cc < 0) ? -f : f;                 // sgn(cnc); sgn(pos) folded into fscl
            r[p] = fmaf(f, fscl[p], base[p]);
        }

        float4* op = reinterpret_cast<float4*>(out + ((size_t)ts * CC + c) * TP);
        op[0] = make_float4(r[0], r[1], r[2], r[3]);
        op[1] = make_float4(r[4], r[5], r[6], r[7]);
    }
}

extern "C" void kernel_launch(void* const* d_in, const int* in_sizes, int n_in,
                              void* d_out, int out_size)
{
    const int*   sta = (const int*)d_in[0];
    const int*   pos = (const int*)d_in[1];
    const int*   cnc = (const int*)d_in[2];
    const float* eu  = (const float*)d_in[3];
    float*       out = (float*)d_out;

    critigraph_kernel<<<TT * SS, 256>>>(sta, pos, cnc, eu, out);
}